// round 15
// baseline (speedup 1.0000x reference)
#include <cuda_runtime.h>
#include <stdint.h>
#include <math.h>

#define NB 128      // batch
#define NTT 32      // timesteps
#define NV 32000    // vocab
#define NE 128      // embed dim
#define NH 256      // hidden
#define NF 2048     // feature dim
#define NG 1024     // 4*H (gates)
#define LDW (NE + NF)   // W_ih row stride = 2176

// ---------------- scratch (device globals; no allocation allowed) ------------
__device__ float g_embed[NTT * NB * NE];       // [t][b][e]
__device__ float g_gembT[NG * NTT * NB];       // [j][t*NB+b]
__device__ float g_gbaseT[NG * NB];            // [j][b] (+both biases folded)
__device__ float g_bpart[8 * NG * NB];         // K-split partials for gbase ([j][b])
__device__ float g_gp[2 * 2 * NG * NB];        // gate partials [parity][kz][j*NB+b]
__device__ float g_cbuf[2 * NH * NB];          // c ping-pong [parity][h*NB+b]
__device__ float g_hT[NH * NB];                // h0 transposed [h][b]
__device__ float g_Hall[NTT * NB * NH];        // [t][b][h] for fc
__device__ float g_initpart[2 * 8 * NB * NH];  // K-split partials for h0/c0 ([b][h])

// ---------------- helpers ----------------------------------------------------
__device__ __forceinline__ uint32_t f2tf32(float x) {
    uint32_t u;
    asm("cvt.rna.tf32.f32 %0, %1;" : "=r"(u) : "f"(x));
    return u;
}

__device__ __forceinline__ void mma_tf32(float* d, const uint32_t* a, const uint32_t* b) {
    asm volatile(
        "mma.sync.aligned.m16n8k8.row.col.f32.tf32.tf32.f32 "
        "{%0,%1,%2,%3}, {%4,%5,%6,%7}, {%8,%9}, {%0,%1,%2,%3};"
        : "+f"(d[0]), "+f"(d[1]), "+f"(d[2]), "+f"(d[3])
        : "r"(a[0]), "r"(a[1]), "r"(a[2]), "r"(a[3]), "r"(b[0]), "r"(b[1]));
}

__device__ __forceinline__ float sigm(float x) {
    return __fdividef(1.f, 1.f + __expf(-x));
}
__device__ __forceinline__ float tanh_f(float x) {
    return 2.f * __fdividef(1.f, 1.f + __expf(-2.f * x)) - 1.f;
}

// LSTM cell from 4 pre-activation gates
__device__ __forceinline__ void lstm_cell(float xi, float xf, float xg, float xo,
                                          float c_old, float& c_new, float& h_new) {
    float i_ = sigm(xi);
    float f_ = sigm(xf);
    float gg = tanh_f(xg);
    float o_ = sigm(xo);
    c_new = f_ * c_old + i_ * gg;
    h_new = o_ * tanh_f(c_new);
}

// ---------------- gather: g_embed[(t*NB+b)*NE + e] = embeddings[captions[b,t]] ----
__global__ void gather_embed_kernel(const int* __restrict__ captions,
                                    const float* __restrict__ embeddings) {
    int idx = blockIdx.x * blockDim.x + threadIdx.x;
    if (idx >= NTT * NB * NE) return;
    int e = idx % NE;
    int m = idx / NE;          // t*NB + b
    int t = m / NB;
    int b = m % NB;
    int tok = captions[b * NTT + t];
    g_embed[idx] = embeddings[tok * NE + e];
}

// ---------------- init h0/c0: NN gemm with deterministic K-split -------------
__global__ void init_part_kernel(const float* __restrict__ A,   // features (NB, NF)
                                 const float* __restrict__ W,   // (NF, NH)
                                 int mat) {
    __shared__ float As[16][64];
    __shared__ float Bs[16][64];
    int n0 = blockIdx.x * 64;
    int m0 = blockIdx.y * 64;
    int kz = blockIdx.z;
    int tid = threadIdx.x;
    int lm = tid >> 2, lk = (tid & 3) * 4;
    int kr = tid >> 4, n4 = (tid & 15) * 4;
    int tx = tid & 15, ty = tid >> 4;
    float acc[4][4] = {};

    for (int k0 = kz * 256; k0 < kz * 256 + 256; k0 += 16) {
        float4 av = *(const float4*)&A[(size_t)(m0 + lm) * NF + k0 + lk];
        As[lk + 0][lm] = av.x; As[lk + 1][lm] = av.y;
        As[lk + 2][lm] = av.z; As[lk + 3][lm] = av.w;
        float4 bv = *(const float4*)&W[(size_t)(k0 + kr) * NH + n0 + n4];
        *(float4*)&Bs[kr][n4] = bv;
        __syncthreads();
        #pragma unroll
        for (int kk = 0; kk < 16; kk++) {
            float4 a = *(const float4*)&As[kk][ty * 4];
            float4 b = *(const float4*)&Bs[kk][tx * 4];
            float ar[4] = {a.x, a.y, a.z, a.w};
            float br[4] = {b.x, b.y, b.z, b.w};
            #pragma unroll
            for (int i = 0; i < 4; i++)
                #pragma unroll
                for (int j = 0; j < 4; j++)
                    acc[i][j] = fmaf(ar[i], br[j], acc[i][j]);
        }
        __syncthreads();
    }
    float* dst = g_initpart + ((size_t)(mat * 8 + kz) * NB) * NH;
    #pragma unroll
    for (int i = 0; i < 4; i++)
        #pragma unroll
        for (int j = 0; j < 4; j++)
            dst[(size_t)(m0 + ty * 4 + i) * NH + n0 + tx * 4 + j] = acc[i][j];
}

// reduce [b][h] partials -> g_hT [h][b], g_cbuf[0] [h][b]
__global__ void init_reduce_kernel(const float* __restrict__ bH,
                                   const float* __restrict__ bC) {
    int idx = blockIdx.x * blockDim.x + threadIdx.x;   // over [b][h]
    int b = idx >> 8;
    int h = idx & 255;
    float sH = bH[h], sC = bC[h];
    #pragma unroll
    for (int z = 0; z < 8; z++) {
        sH += g_initpart[(size_t)z * NB * NH + idx];
        sC += g_initpart[(size_t)(8 + z) * NB * NH + idx];
    }
    g_hT[h * NB + b] = sH;
    g_cbuf[h * NB + b] = sC;    // parity 0
}

// ---------------- generic NT sgemm: C[M,N] = A(M,K) @ B(N,K)^T ---------------
__global__ void sgemm_nt64(const float* __restrict__ A, int lda,
                           const float* __restrict__ B, int ldb,
                           float* __restrict__ C, int ldc, int K) {
    __shared__ float As[16][64];
    __shared__ float Bs[16][64];
    int m0 = blockIdx.y * 64;
    int n0 = blockIdx.x * 64;
    int tid = threadIdx.x;
    int lm = tid >> 2;
    int lk = (tid & 3) * 4;
    int tx = tid & 15;
    int ty = tid >> 4;
    float acc[4][4] = {};

    for (int k0 = 0; k0 < K; k0 += 16) {
        float4 av = *(const float4*)&A[(size_t)(m0 + lm) * lda + k0 + lk];
        float4 bv = *(const float4*)&B[(size_t)(n0 + lm) * ldb + k0 + lk];
        As[lk + 0][lm] = av.x; As[lk + 1][lm] = av.y;
        As[lk + 2][lm] = av.z; As[lk + 3][lm] = av.w;
        Bs[lk + 0][lm] = bv.x; Bs[lk + 1][lm] = bv.y;
        Bs[lk + 2][lm] = bv.z; Bs[lk + 3][lm] = bv.w;
        __syncthreads();
        #pragma unroll
        for (int kk = 0; kk < 16; kk++) {
            float4 a = *(const float4*)&As[kk][ty * 4];
            float4 b = *(const float4*)&Bs[kk][tx * 4];
            float ar[4] = {a.x, a.y, a.z, a.w};
            float br[4] = {b.x, b.y, b.z, b.w};
            #pragma unroll
            for (int i = 0; i < 4; i++)
                #pragma unroll
                for (int j = 0; j < 4; j++)
                    acc[i][j] = fmaf(ar[i], br[j], acc[i][j]);
        }
        __syncthreads();
    }

    #pragma unroll
    for (int i = 0; i < 4; i++)
        #pragma unroll
        for (int j = 0; j < 4; j++)
            C[(size_t)(m0 + ty * 4 + i) * ldc + n0 + tx * 4 + j] = acc[i][j];
}

// ---------------- gates_base: K-split NT gemm (M=NG j-rows, N=NB, K=2048) ----
__global__ void gbase_part_kernel(const float* __restrict__ A,   // W_ih + NE, lda=LDW
                                  const float* __restrict__ B) { // features, ldb=NF
    __shared__ float As[16][64];
    __shared__ float Bs[16][64];
    int n0 = blockIdx.x * 64;   // b
    int m0 = blockIdx.y * 64;   // j
    int kz = blockIdx.z;
    int tid = threadIdx.x;
    int lm = tid >> 2;
    int lk = (tid & 3) * 4;
    int tx = tid & 15;
    int ty = tid >> 4;
    float acc[4][4] = {};

    for (int k0 = kz * 256; k0 < kz * 256 + 256; k0 += 16) {
        float4 av = *(const float4*)&A[(size_t)(m0 + lm) * LDW + k0 + lk];
        float4 bv = *(const float4*)&B[(size_t)(n0 + lm) * NF + k0 + lk];
        As[lk + 0][lm] = av.x; As[lk + 1][lm] = av.y;
        As[lk + 2][lm] = av.z; As[lk + 3][lm] = av.w;
        Bs[lk + 0][lm] = bv.x; Bs[lk + 1][lm] = bv.y;
        Bs[lk + 2][lm] = bv.z; Bs[lk + 3][lm] = bv.w;
        __syncthreads();
        #pragma unroll
        for (int kk = 0; kk < 16; kk++) {
            float4 a = *(const float4*)&As[kk][ty * 4];
            float4 b = *(const float4*)&Bs[kk][tx * 4];
            float ar[4] = {a.x, a.y, a.z, a.w};
            float br[4] = {b.x, b.y, b.z, b.w};
            #pragma unroll
            for (int i = 0; i < 4; i++)
                #pragma unroll
                for (int j = 0; j < 4; j++)
                    acc[i][j] = fmaf(ar[i], br[j], acc[i][j]);
        }
        __syncthreads();
    }
    float* dst = g_bpart + (size_t)kz * NG * NB;
    #pragma unroll
    for (int i = 0; i < 4; i++)
        #pragma unroll
        for (int j = 0; j < 4; j++)
            dst[(size_t)(m0 + ty * 4 + i) * NB + n0 + tx * 4 + j] = acc[i][j];
}

// reduce partials -> g_gbaseT [j][b], folding both biases
__global__ void gbase_reduce_kernel(const float* __restrict__ bih,
                                    const float* __restrict__ bhh) {
    int idx = blockIdx.x * blockDim.x + threadIdx.x;   // over NG*NB, [j][b]
    int j = idx >> 7;
    float s = bih[j] + bhh[j];
    #pragma unroll
    for (int z = 0; z < 8; z++)
        s += g_bpart[(size_t)z * NG * NB + idx];
    g_gbaseT[idx] = s;
}

// ---------------- fused step kernel ------------------------------------------
// Step t (t=0..31): obtain h_t (t=0: from g_hT; t>0: cell on gates_{t-1} partials),
// then compute gate partials for step t: gp[t&1][kz][j][b] = h_t[b,kz-half] @ W_hh[j,kz-half]^T
// (+ gbaseT + gembT[t] folded into kz==0 partial).
// Grid: (16 j-tiles, 4 b-tiles of 32, 2 K-halves) = 128 CTAs, 256 threads.
__global__ void __launch_bounds__(256) step_kernel(const float* __restrict__ W_hh,
                                                   float* __restrict__ Hall, int t) {
    __shared__ float h_sm[128][34];    // [k=hloc][b], stride 34 (8B-aligned float2)
    __shared__ float Bs[2][16][68];    // W_hh tile [k][j], stride 68 floats = 272B (16B-aligned float4)
    const int n0 = blockIdx.x * 64;    // j tile
    const int m0 = blockIdx.y * 32;    // b tile
    const int kz = blockIdx.z;         // K half
    const int tid = threadIdx.x;

    // ---- phase 1: materialize h for this CTA's (32 b x 128 h-half) ----
    if (t == 0) {
        for (int i = tid; i < 128 * 32; i += 256) {
            int hl = i >> 5, b = i & 31;
            h_sm[hl][b] = g_hT[(kz * 128 + hl) * NB + m0 + b];
        }
    } else {
        const int p = (t - 1) & 1;
        const float* gp0 = g_gp + (size_t)(p * 2 + 0) * NG * NB;
        const float* gp1 = g_gp + (size_t)(p * 2 + 1) * NG * NB;
        const float* cr = g_cbuf + (size_t)((t - 1) & 1) * NH * NB;
        float* cw = g_cbuf + (size_t)(t & 1) * NH * NB;
        const bool writer = (blockIdx.x == 0);
        const int b = tid & 31;
        const int hg = tid >> 5;           // 8 groups
        const int gb = m0 + b;
        #pragma unroll 4
        for (int i = 0; i < 16; i++) {
            int hl = hg + 8 * i;
            int h = kz * 128 + hl;
            float xi = gp0[(0 * NH + h) * NB + gb] + gp1[(0 * NH + h) * NB + gb];
            float xf = gp0[(1 * NH + h) * NB + gb] + gp1[(1 * NH + h) * NB + gb];
            float xg = gp0[(2 * NH + h) * NB + gb] + gp1[(2 * NH + h) * NB + gb];
            float xo = gp0[(3 * NH + h) * NB + gb] + gp1[(3 * NH + h) * NB + gb];
            float c_old = cr[h * NB + gb];
            float cn, hn;
            lstm_cell(xi, xf, xg, xo, c_old, cn, hn);
            h_sm[hl][b] = hn;
            if (writer) {
                cw[h * NB + gb] = cn;
                Hall[((size_t)(t - 1) * NB + gb) * NH + h] = hn;
            }
        }
    }

    // ---- phase 2: GEMM 32(b) x 64(j) x 128(k) ----
    const int jr = tid >> 2;            // 0..63
    const int k4 = (tid & 3) * 4;       // 0,4,8,12
    const float* wp = W_hh + (size_t)(n0 + jr) * NH + kz * 128 + k4;
    const int tx = tid & 15, ty = tid >> 4;
    const int j4 = tx * 4, b2 = ty * 2;

    float4 wv = *(const float4*)wp;
    Bs[0][k4 + 0][jr] = wv.x; Bs[0][k4 + 1][jr] = wv.y;
    Bs[0][k4 + 2][jr] = wv.z; Bs[0][k4 + 3][jr] = wv.w;
    __syncthreads();

    float acc[2][4] = {};
    #pragma unroll 1
    for (int kc = 0; kc < 128; kc += 16) {
        const int cur = (kc >> 4) & 1;
        if (kc < 112)
            wv = *(const float4*)(wp + kc + 16);
        #pragma unroll
        for (int k = 0; k < 16; k++) {
            float2 hv = *(const float2*)&h_sm[kc + k][b2];
            float4 bv = *(const float4*)&Bs[cur][k][j4];
            acc[0][0] = fmaf(hv.x, bv.x, acc[0][0]);
            acc[0][1] = fmaf(hv.x, bv.y, acc[0][1]);
            acc[0][2] = fmaf(hv.x, bv.z, acc[0][2]);
            acc[0][3] = fmaf(hv.x, bv.w, acc[0][3]);
            acc[1][0] = fmaf(hv.y, bv.x, acc[1][0]);
            acc[1][1] = fmaf(hv.y, bv.y, acc[1][1]);
            acc[1][2] = fmaf(hv.y, bv.z, acc[1][2]);
            acc[1][3] = fmaf(hv.y, bv.w, acc[1][3]);
        }
        if (kc < 112) {
            const int nxt = cur ^ 1;
            Bs[nxt][k4 + 0][jr] = wv.x; Bs[nxt][k4 + 1][jr] = wv.y;
            Bs[nxt][k4 + 2][jr] = wv.z; Bs[nxt][k4 + 3][jr] = wv.w;
        }
        __syncthreads();
    }

    // epilogue -> gp[t&1][kz][j][b]; kz==0 carries gbase+gemb
    float* dst = g_gp + (size_t)((t & 1) * 2 + kz) * NG * NB;
    #pragma unroll
    for (int j = 0; j < 4; j++) {
        int jj = n0 + j4 + j;
        float v0 = acc[0][j], v1 = acc[1][j];
        if (kz == 0) {
            v0 += g_gbaseT[jj * NB + m0 + b2]
                + g_gembT[(size_t)jj * (NTT * NB) + t * NB + m0 + b2];
            v1 += g_gbaseT[jj * NB + m0 + b2 + 1]
                + g_gembT[(size_t)jj * (NTT * NB) + t * NB + m0 + b2 + 1];
        }
        float2 v = {v0, v1};
        *(float2*)&dst[(size_t)jj * NB + m0 + b2] = v;
    }
}

// ---------------- final cell: Hall[31] from gates_31 -------------------------
__global__ void final_cell_kernel(float* __restrict__ Hall) {
    int i = blockIdx.x * blockDim.x + threadIdx.x;   // NH*NB, [h][b]
    int h = i >> 7, b = i & 127;
    const float* gp0 = g_gp + (size_t)(1 * 2 + 0) * NG * NB;   // parity 31&1=1
    const float* gp1 = g_gp + (size_t)(1 * 2 + 1) * NG * NB;
    float xi = gp0[(0 * NH + h) * NB + b] + gp1[(0 * NH + h) * NB + b];
    float xf = gp0[(1 * NH + h) * NB + b] + gp1[(1 * NH + h) * NB + b];
    float xg = gp0[(2 * NH + h) * NB + b] + gp1[(2 * NH + h) * NB + b];
    float xo = gp0[(3 * NH + h) * NB + b] + gp1[(3 * NH + h) * NB + b];
    float c_old = g_cbuf[(size_t)1 * NH * NB + h * NB + b];    // c_31, parity 1
    float cn, hn;
    lstm_cell(xi, xf, xg, xo, c_old, cn, hn);
    Hall[((size_t)31 * NB + b) * NH + h] = hn;
}

// ---------------- fc: tf32 tensor-core GEMM, fragment-major smem -------------
__global__ void __launch_bounds__(256) fc_tf32_kernel(const float* __restrict__ A,
                                                      const float* __restrict__ Bw,
                                                      const float* __restrict__ bias,
                                                      float* __restrict__ out) {
    __shared__ __align__(16) uint32_t As[2][16 * 132];  // 16 chunks (mb*2+kk), pad 128->132
    __shared__ __align__(16) uint32_t Bs[2][32 * 66];   // 32 chunks (nb*2+kk), pad 64->66
    const int tid = threadIdx.x;
    const int m0 = blockIdx.y * 128, n0 = blockIdx.x * 128;
    const int lane = tid & 31, warp = tid >> 5;
    const int g = lane >> 2, tig = lane & 3;
    const int amb0 = (warp >> 2) * 4;
    const int bnb0 = (warp & 3) * 4;
    const int wm = (warp >> 2) * 64, wn = (warp & 3) * 32;

    const int a_row = tid >> 2;
    const int a_col = (tid & 3) * 4;
    const int b_row = tid >> 5;
    const int b_col = (tid & 31) * 4;
    const float* Ag = A + (size_t)(m0 + a_row) * NH + a_col;
    const float* Bg = Bw + (size_t)b_row * NV + n0 + b_col;

    const int a_mb = a_row >> 4;
    const int a_g = a_row & 7;
    const int a_half = (a_row >> 3) & 1;
    const int a_kk = a_col >> 3;
    const int a_chi = (a_col >> 2) & 1;
    const int a_reg = a_half + 2 * a_chi;
    const int aw0 = (a_mb * 2 + a_kk) * 132 + a_g * 16 + a_reg;
    const int aw1 = ((a_mb + 4) * 2 + a_kk) * 132 + a_g * 16 + a_reg;
    const int b_nb = b_col >> 3;
    const int b_g0 = b_col & 7;
    const int b_tig = b_row & 3;
    const int b_khi = (b_row >> 2) & 1;
    const int bw0 = (b_nb * 2 + 0) * 66 + (b_g0 * 4 + b_tig) * 2 + b_khi;
    const int bw1 = (b_nb * 2 + 1) * 66 + (b_g0 * 4 + b_tig) * 2 + b_khi;

    float acc[4][4][4];
    #pragma unroll
    for (int i = 0; i < 4; i++)
        #pragma unroll
        for (int j = 0; j < 4; j++)
            #pragma unroll
            for (int r = 0; r < 4; r++) acc[i][j][r] = 0.f;

    float4 pa[2], pb[2];
    pa[0] = *(const float4*)(Ag);
    pa[1] = *(const float4*)(Ag + (size_t)64 * NH);
    pb[0] = *(const float4*)(Bg);
    pb[1] = *(const float4*)(Bg + (size_t)8 * NV);
    {
        As[0][aw0] = f2tf32(pa[0].x); As[0][aw0 + 4] = f2tf32(pa[0].y);
        As[0][aw0 + 8] = f2tf32(pa[0].z); As[0][aw0 + 12] = f2tf32(pa[0].w);
        As[0][aw1] = f2tf32(pa[1].x); As[0][aw1 + 4] = f2tf32(pa[1].y);
        As[0][aw1 + 8] = f2tf32(pa[1].z); As[0][aw1 + 12] = f2tf32(pa[1].w);
        Bs[0][bw0] = f2tf32(pb[0].x); Bs[0][bw0 + 8] = f2tf32(pb[0].y);
        Bs[0][bw0 + 16] = f2tf32(pb[0].z); Bs[0][bw0 + 24] = f2tf32(pb[0].w);
        Bs[0][bw1] = f2tf32(pb[1].x); Bs[0][bw1 + 8] = f2tf32(pb[1].y);
        Bs[0][bw1 + 16] = f2tf32(pb[1].z); Bs[0][bw1 + 24] = f2tf32(pb[1].w);
    }
    __syncthreads();

    #pragma unroll 1
    for (int it = 0; it < 16; it++) {
        const int cur = it & 1;
        if (it < 15) {
            const int k0 = (it + 1) * 16;
            pa[0] = *(const float4*)(Ag + k0);
            pa[1] = *(const float4*)(Ag + (size_t)64 * NH + k0);
            pb[0] = *(const float4*)(Bg + (size_t)k0 * NV);
            pb[1] = *(const float4*)(Bg + (size_t)(k0 + 8) * NV);
        }
        #pragma unroll
        for (int kk = 0; kk < 2; kk++) {
            uint4 af[4];
            uint2 bf[4];
            #pragma unroll
            for (int ti = 0; ti < 4; ti++)
                af[ti] = *(const uint4*)&As[cur][((amb0 + ti) * 2 + kk) * 132 + lane * 4];
            #pragma unroll
            for (int tj = 0; tj < 4; tj++)
                bf[tj] = *(const uint2*)&Bs[cur][((bnb0 + tj) * 2 + kk) * 66 + lane * 2];
            #pragma unroll
            for (int ti = 0; ti < 4; ti++)
                #pragma unroll
                for (int tj = 0; tj < 4; tj++)
                    mma_tf32(acc[ti][tj],
                             reinterpret_cast<const uint32_t*>(&af[ti]),
                             reinterpret_cast<const uint32_t*>(&bf[tj]));
        }
        if (it < 15) {
            const int nb = cur ^ 1;
            As[nb][aw0] = f2tf32(pa[0].x); As[nb][aw0 + 4] = f2tf32(pa[0].y);
            As[nb][aw0 + 8] = f2tf32(pa[0].z); As[nb][aw0 + 12] = f2tf32(pa[0].w);
            As[nb][aw1] = f2tf32(pa[1].x); As[nb][aw1 + 4] = f2tf32(pa[1].y);
            As[nb][aw1 + 8] = f2tf32(pa[1].z); As[nb][aw1 + 12] = f2tf32(pa[1].w);
            Bs[nb][bw0] = f2tf32(pb[0].x); Bs[nb][bw0 + 8] = f2tf32(pb[0].y);
            Bs[nb][bw0 + 16] = f2tf32(pb[0].z); Bs[nb][bw0 + 24] = f2tf32(pb[0].w);
            Bs[nb][bw1] = f2tf32(pb[1].x); Bs[nb][bw1 + 8] = f2tf32(pb[1].y);
            Bs[nb][bw1 + 16] = f2tf32(pb[1].z); Bs[nb][bw1 + 24] = f2tf32(pb[1].w);
        }
        __syncthreads();
    }

    #pragma unroll
    for (int ti = 0; ti < 4; ti++) {
        int mA = m0 + wm + ti * 16 + g;
        int mB = mA + 8;
        int tA = mA >> 7, bA = mA & 127;
        int tB = mB >> 7, bB = mB & 127;
        float* oA = out + (size_t)(bA * NTT + tA) * NV;
        float* oB = out + (size_t)(bB * NTT + tB) * NV;
        #pragma unroll
        for (int tj = 0; tj < 4; tj++) {
            int n = n0 + wn + tj * 8 + 2 * tig;
            float b0 = bias[n], b1 = bias[n + 1];
            float2 vA, vB;
            vA.x = acc[ti][tj][0] + b0; vA.y = acc[ti][tj][1] + b1;
            vB.x = acc[ti][tj][2] + b0; vB.y = acc[ti][tj][3] + b1;
            *(float2*)&oA[n] = vA;
            *(float2*)&oB[n] = vB;
        }
    }
}

// ---------------- launch ----------------------------------------------------
extern "C" void kernel_launch(void* const* d_in, const int* in_sizes, int n_in,
                              void* d_out, int out_size) {
    const float* features   = (const float*)d_in[0];
    const int*   captions   = (const int*)d_in[1];
    const float* embeddings = (const float*)d_in[2];
    const float* W_ih       = (const float*)d_in[3];
    const float* b_ih       = (const float*)d_in[4];
    const float* W_hh       = (const float*)d_in[5];
    const float* b_hh       = (const float*)d_in[6];
    const float* fc_W       = (const float*)d_in[7];
    const float* fc_b       = (const float*)d_in[8];
    // d_in[9..14] = attention weights: provably unused (softmax over length-1 axis == 1)
    const float* initH_W    = (const float*)d_in[15];
    const float* initH_b    = (const float*)d_in[16];
    const float* initC_W    = (const float*)d_in[17];
    const float* initC_b    = (const float*)d_in[18];
    float* out = (float*)d_out;

    void *p_embed_, *p_gembT_, *p_Hall_;
    cudaGetSymbolAddress(&p_embed_, g_embed);
    cudaGetSymbolAddress(&p_gembT_, g_gembT);
    cudaGetSymbolAddress(&p_Hall_,  g_Hall);
    float* p_embed = (float*)p_embed_;
    float* p_gembT = (float*)p_gembT_;
    float* p_Hall  = (float*)p_Hall_;

    // 1) gather word embeddings
    gather_embed_kernel<<<(NTT * NB * NE + 255) / 256, 256>>>(captions, embeddings);

    // 2) gembT[j][t*NB+b] = W_ih[j,:E] . embed[t,b,:]   (M=1024 j, N=4096, K=128)
    sgemm_nt64<<<dim3((NTT * NB) / 64, NG / 64), 256>>>(
        W_ih, LDW, p_embed, NE, p_gembT, NTT * NB, NE);

    // 3) gbaseT[j][b]: K-split GEMM + deterministic reduce (+both biases)
    gbase_part_kernel<<<dim3(NB / 64, NG / 64, 8), 256>>>(W_ih + NE, features);
    gbase_reduce_kernel<<<(NG * NB) / 256, 256>>>(b_ih, b_hh);

    // 4) h0, c0 via K-split GEMM + deterministic reduce (writes g_hT, g_cbuf[0])
    init_part_kernel<<<dim3(NH / 64, NB / 64, 8), 256>>>(features, initH_W, 0);
    init_part_kernel<<<dim3(NH / 64, NB / 64, 8), 256>>>(features, initC_W, 1);
    init_reduce_kernel<<<NB, NH>>>(initH_b, initC_b);

    // 5) fused recurrence: 32 step kernels (cell + gates GEMM), full-chip grids
    for (int t = 0; t < NTT; t++)
        step_kernel<<<dim3(16, 4, 2), 256>>>(W_hh, p_Hall, t);
    final_cell_kernel<<<(NH * NB) / 256, 256>>>(p_Hall);

    // 6) fc projection: tf32 tensor-core GEMM (4096, 256) @ (256, 32000)
    fc_tf32_kernel<<<dim3(NV / 128, (NTT * NB) / 128), 256>>>(p_Hall, fc_W, fc_b, out);
}